// round 6
// baseline (speedup 1.0000x reference)
#include <cuda_runtime.h>
#include <cstdint>

#define BATCH 2
#define SEQ 4096
#define NH 16
#define DK 64
#define DM 1024
#define L2E 1.4426950408889634f

// ---------------- scratch (no allocation allowed) ----------------
__device__ float g_Q[(size_t)BATCH * NH * SEQ * DK];
__device__ float g_K[(size_t)BATCH * NH * SEQ * DK];
__device__ float g_V[(size_t)BATCH * NH * SEQ * DK];
__device__ float g_A[(size_t)BATCH * SEQ * DM];
__device__ float g_Xr[(size_t)BATCH * SEQ * DM];   // tf32-rounded x
__device__ float g_Wr[(size_t)4 * DM * DM];        // tf32-rounded Wq,Wk,Wv,Wo

// ---------------- helpers ----------------
__device__ __forceinline__ uint32_t f2tf(float x) {
    uint32_t r;
    asm("cvt.rna.tf32.f32 %0, %1;" : "=r"(r) : "f"(x));
    return r;
}
__device__ __forceinline__ float f2tff(float x) {
    return __uint_as_float(f2tf(x));
}
__device__ __forceinline__ uint32_t smem_u32(const void* p) {
    uint32_t a;
    asm("{ .reg .u64 t; cvta.to.shared.u64 t, %1; cvt.u32.u64 %0, t; }"
        : "=r"(a) : "l"(p));
    return a;
}
__device__ __forceinline__ void cp16(uint32_t dst, const void* src) {
    asm volatile("cp.async.cg.shared.global [%0], [%1], 16;" :: "r"(dst), "l"(src));
}
__device__ __forceinline__ void cp_commit() {
    asm volatile("cp.async.commit_group;" ::: "memory");
}
template <int N>
__device__ __forceinline__ void cp_wait() {
    asm volatile("cp.async.wait_group %0;" :: "n"(N) : "memory");
}
__device__ __forceinline__ uint32_t swz(uint32_t off) {
    return off ^ ((off >> 3) & 0x70);
}
__device__ __forceinline__ void mma_tf32(float c[4], uint32_t a0, uint32_t a1,
                                         uint32_t a2, uint32_t a3,
                                         uint32_t b0, uint32_t b1) {
    asm volatile(
        "mma.sync.aligned.m16n8k8.row.col.f32.tf32.tf32.f32 "
        "{%0,%1,%2,%3}, {%4,%5,%6,%7}, {%8,%9}, {%0,%1,%2,%3};"
        : "+f"(c[0]), "+f"(c[1]), "+f"(c[2]), "+f"(c[3])
        : "r"(a0), "r"(a1), "r"(a2), "r"(a3), "r"(b0), "r"(b1));
}

// ---------------- pre-round x + all W to tf32 (rna) ----------------
__global__ __launch_bounds__(256) void round_tf32_kernel(
    const float* __restrict__ x, const float* __restrict__ Wq,
    const float* __restrict__ Wk, const float* __restrict__ Wv,
    const float* __restrict__ Wo) {
    size_t i4 = (size_t)blockIdx.x * 256 + threadIdx.x;  // float4 index
    const float4* src;
    float4* dst;
    if (i4 < 2097152) {
        src = (const float4*)x + i4;
        dst = (float4*)g_Xr + i4;
    } else {
        size_t r = i4 - 2097152;
        int j = (int)(r >> 18);
        size_t o = r & 262143;
        const float* w = (j == 0) ? Wq : (j == 1) ? Wk : (j == 2) ? Wv : Wo;
        src = (const float4*)w + o;
        dst = (float4*)g_Wr + (size_t)j * 262144 + o;
    }
    float4 v = *src;
    float4 u;
    u.x = f2tff(v.x); u.y = f2tff(v.y); u.z = f2tff(v.z); u.w = f2tff(v.w);
    *dst = u;
}

// ---------------- mma.sync tf32 GEMM, cp.async 3-stage ring ----------------
// C = A(Mx1024) * W(1024x1024)^T, tile 128x128, 256 thr, warp tile 64x32.
// Inputs MUST be pre-rounded to tf32 (fed raw into HMMA).
// MODE 0: row-major C[M][1024] (fp32).  MODE 1: scatter [b][h][s][64], tf32-rounded.
#define STAGE_BYTES 32768           // A slab 16KB + W slab 16KB
#define GEMM_SMEM (1024 + 3 * STAGE_BYTES)

template <int MODE>
__global__ __launch_bounds__(256, 2) void gemm_mma(
    const float* __restrict__ Abase, const float* __restrict__ Wbase,
    float* __restrict__ C0, float* __restrict__ C1, float* __restrict__ C2) {
    extern __shared__ char smraw[];
    const uint32_t smem0 = smem_u32(smraw);
    const uint32_t base = (smem0 + 1023) & ~1023u;
    char* bp = smraw + (base - smem0);

    const int tid = threadIdx.x, wid = tid >> 5, lane = tid & 31;
    const int g = lane >> 2, tig = lane & 3;
    const int wm = (wid & 1) * 64, wn = (wid >> 1) * 32;
    const int z = blockIdx.z;
    const int m0 = blockIdx.y * 128, n0 = blockIdx.x * 128;
    const float* W = Wbase + (size_t)z * (DM * DM);
    float* C = (z == 0) ? C0 : (z == 1) ? C1 : C2;

    float acc[4][4][4];
#pragma unroll
    for (int mt = 0; mt < 4; mt++)
#pragma unroll
        for (int nt = 0; nt < 4; nt++)
#pragma unroll
            for (int k = 0; k < 4; k++) acc[mt][nt][k] = 0.f;

    // slab fill: A tile 128x32 (16KB) + W tile 128x32 (16KB), swizzled 128B rows
    auto fill = [&](int s) {
        const uint32_t st = base + (uint32_t)(s % 3) * STAGE_BYTES;
        const int kb = s * 32;
#pragma unroll
        for (int i = 0; i < 4; i++) {  // A: 1024 16B-chunks
            int q = tid + i * 256;
            int r = q >> 3, c = q & 7;
            cp16(st + swz(r * 128 + c * 16),
                 Abase + (size_t)(m0 + r) * DM + kb + c * 4);
        }
#pragma unroll
        for (int i = 0; i < 4; i++) {  // W: 1024 16B-chunks
            int q = tid + i * 256;
            int r = q >> 3, c = q & 7;
            cp16(st + 16384 + swz(r * 128 + c * 16),
                 W + (size_t)(n0 + r) * DM + kb + c * 4);
        }
        cp_commit();
    };

    fill(0); fill(1); fill(2);

    for (int s = 0; s < 32; s++) {
        cp_wait<2>();
        __syncthreads();
        const char* st = bp + (size_t)(s % 3) * STAGE_BYTES;
        const char* wt = st + 16384;
#pragma unroll
        for (int kk = 0; kk < 32; kk += 8) {
            uint32_t a[4][4], b[4][2];
#pragma unroll
            for (int mt = 0; mt < 4; mt++) {
                int r = wm + mt * 16;
                a[mt][0] = *(const uint32_t*)(st + swz((r + g) * 128 + (kk + tig) * 4));
                a[mt][1] = *(const uint32_t*)(st + swz((r + g + 8) * 128 + (kk + tig) * 4));
                a[mt][2] = *(const uint32_t*)(st + swz((r + g) * 128 + (kk + tig + 4) * 4));
                a[mt][3] = *(const uint32_t*)(st + swz((r + g + 8) * 128 + (kk + tig + 4) * 4));
            }
#pragma unroll
            for (int nt = 0; nt < 4; nt++) {
                int cn = wn + nt * 8 + g;
                b[nt][0] = *(const uint32_t*)(wt + swz(cn * 128 + (kk + tig) * 4));
                b[nt][1] = *(const uint32_t*)(wt + swz(cn * 128 + (kk + tig + 4) * 4));
            }
#pragma unroll
            for (int mt = 0; mt < 4; mt++)
#pragma unroll
                for (int nt = 0; nt < 4; nt++)
                    mma_tf32(acc[mt][nt], a[mt][0], a[mt][1], a[mt][2], a[mt][3],
                             b[nt][0], b[nt][1]);
        }
        __syncthreads();
        if (s + 3 < 32) fill(s + 3);
    }

#pragma unroll
    for (int mt = 0; mt < 4; mt++) {
#pragma unroll
        for (int nt = 0; nt < 4; nt++) {
            int r0 = m0 + wm + mt * 16 + g;
            int r1 = r0 + 8;
            int cc = n0 + wn + nt * 8 + 2 * tig;
            if (MODE == 0) {
                *(float2*)&C[(size_t)r0 * DM + cc] =
                    make_float2(acc[mt][nt][0], acc[mt][nt][1]);
                *(float2*)&C[(size_t)r1 * DM + cc] =
                    make_float2(acc[mt][nt][2], acc[mt][nt][3]);
            } else {
                int h = cc >> 6, d = cc & 63;
                int b0i = r0 >> 12, s0 = r0 & (SEQ - 1);
                int b1i = r1 >> 12, s1 = r1 & (SEQ - 1);
                *(float2*)&C[((size_t)(b0i * NH + h) * SEQ + s0) * DK + d] =
                    make_float2(f2tff(acc[mt][nt][0]), f2tff(acc[mt][nt][1]));
                *(float2*)&C[((size_t)(b1i * NH + h) * SEQ + s1) * DK + d] =
                    make_float2(f2tff(acc[mt][nt][2]), f2tff(acc[mt][nt][3]));
            }
        }
    }
}

// ---------------- RoPE (in-place; folds Q-scale; rounds to tf32) ----------
__global__ void rope_kernel(float* __restrict__ Q, float* __restrict__ K,
                            const int* __restrict__ pos) {
    const int NPAIR = BATCH * NH * SEQ * (DK / 2);
    int i = blockIdx.x * blockDim.x + threadIdx.x;
    if (i >= NPAIR) return;
    int j = i & 31;
    int s = (i >> 5) & (SEQ - 1);
    int h = (i >> 17) & (NH - 1);
    int b = i >> 21;

    const bool isQ = (blockIdx.y == 0);
    float* ptr = isQ ? Q : K;
    int p = pos[b * SEQ + s];
    float freq = exp2f(-(float)j * (13.287712379549449f / 32.f));
    float ang = (float)p * freq;
    float sn, cs;
    sincosf(ang, &sn, &cs);

    size_t basei = ((size_t)(b * NH + h) * SEQ + s) * DK + 2 * j;
    float e = ptr[basei];
    float o = ptr[basei + 1];
    float ne = e * cs - o * sn;
    float no = e * sn + o * cs;
    if (isQ) {
        const float qscale = 0.125f * L2E;
        ne *= qscale;
        no *= qscale;
    }
    ptr[basei] = f2tff(ne);
    ptr[basei + 1] = f2tff(no);
}

// ---------------- causal flash attention, tf32 mma.sync, cp.async KV ------
// grid (64 q-tiles, 16 heads, 2 batch); 128 threads = 4 warps x 16 rows.
// smem u32: Qs[64*68] | Ks0 | Ks1 [64*68 each] | Vs0 | Vs1 [64*72] | Ps[64*68]
#define QS_OFF 0
#define KS_OFF 4352
#define VS_OFF (4352 + 2 * 4352)
#define PS_OFF (4352 + 2 * 4352 + 2 * 4608)
#define ATT_SMEM ((4352 + 2 * 4352 + 2 * 4608 + 4352) * 4)

__global__ __launch_bounds__(128) void attn_tf32(const float* __restrict__ gQ,
                                                 const float* __restrict__ gK,
                                                 const float* __restrict__ gV,
                                                 float* __restrict__ gO) {
    extern __shared__ uint32_t sm[];
    uint32_t* Qs = sm + QS_OFF;
    uint32_t* Ps = sm + PS_OFF;
    const uint32_t smb = smem_u32(sm);

    const int qt = 63 - (int)blockIdx.x;
    const int h = blockIdx.y;
    const int b = blockIdx.z;
    const int tid = threadIdx.x;
    const int wid = tid >> 5, lane = tid & 31;
    const int g = lane >> 2, tig = lane & 3;
    const int wr = wid * 16;

    const size_t bh = (size_t)(b * NH + h) * SEQ;
    const float* Qb = gQ + (bh + (size_t)qt * 64) * DK;
    const float* Kb = gK + bh * DK;
    const float* Vb = gV + bh * DK;

    // prefetch K/V tile kt into buffer buf (raw, pre-rounded tf32 bits)
    auto prefetch = [&](int kt, int buf) {
        const uint32_t kst = smb + (KS_OFF + buf * 4352) * 4;
        const uint32_t vst = smb + (VS_OFF + buf * 4608) * 4;
#pragma unroll
        for (int i = 0; i < 8; i++) {  // 1024 chunks K
            int q = tid + i * 128;
            int r = q >> 4, c = q & 15;
            cp16(kst + (r * 68 + c * 4) * 4,
                 Kb + (size_t)(kt * 64 + r) * DK + c * 4);
        }
#pragma unroll
        for (int i = 0; i < 8; i++) {  // 1024 chunks V
            int q = tid + i * 128;
            int r = q >> 4, c = q & 15;
            cp16(vst + (r * 72 + c * 4) * 4,
                 Vb + (size_t)(kt * 64 + r) * DK + c * 4);
        }
        cp_commit();
    };

    // load Q tile (already scaled + tf32-rounded by rope)
#pragma unroll
    for (int p = 0; p < 8; p++) {
        int idx = p * 128 + tid;
        int r = idx >> 4, c4 = (idx & 15) * 4;
        float4 v = *(const float4*)(Qb + (size_t)r * DK + c4);
        uint32_t* qp = &Qs[r * 68 + c4];
        qp[0] = __float_as_uint(v.x); qp[1] = __float_as_uint(v.y);
        qp[2] = __float_as_uint(v.z); qp[3] = __float_as_uint(v.w);
    }

    prefetch(0, 0);

    float oacc[8][4];
    float m0 = -1e30f, m1 = -1e30f, l0 = 0.f, l1 = 0.f;
#pragma unroll
    for (int nt = 0; nt < 8; nt++)
#pragma unroll
        for (int k = 0; k < 4; k++) oacc[nt][k] = 0.f;

    const int ntiles = qt + 1;
    for (int kt = 0; kt < ntiles; kt++) {
        const int buf = kt & 1;
        __syncthreads();  // all warps done reading buf (from iter kt-2) & Ps
        if (kt + 1 < ntiles) {
            prefetch(kt + 1, buf ^ 1);
            cp_wait<1>();
        } else {
            cp_wait<0>();
        }
        __syncthreads();  // buf kt visible to all

        const uint32_t* Ks = sm + KS_OFF + buf * 4352;
        const uint32_t* Vs = sm + VS_OFF + buf * 4608;

        float sacc[8][4];
#pragma unroll
        for (int nt = 0; nt < 8; nt++)
#pragma unroll
            for (int k = 0; k < 4; k++) sacc[nt][k] = 0.f;

#pragma unroll
        for (int kk = 0; kk < 64; kk += 8) {
            uint32_t a0 = Qs[(wr + g) * 68 + kk + tig];
            uint32_t a1 = Qs[(wr + g + 8) * 68 + kk + tig];
            uint32_t a2 = Qs[(wr + g) * 68 + kk + tig + 4];
            uint32_t a3 = Qs[(wr + g + 8) * 68 + kk + tig + 4];
#pragma unroll
            for (int nt = 0; nt < 8; nt++) {
                uint32_t b0 = Ks[(nt * 8 + g) * 68 + kk + tig];
                uint32_t b1 = Ks[(nt * 8 + g) * 68 + kk + tig + 4];
                mma_tf32(sacc[nt], a0, a1, a2, a3, b0, b1);
            }
        }

        if (kt == qt) {
#pragma unroll
            for (int nt = 0; nt < 8; nt++) {
                int c0 = nt * 8 + 2 * tig, c1 = c0 + 1;
                if (c0 > wr + g) sacc[nt][0] = -1e30f;
                if (c1 > wr + g) sacc[nt][1] = -1e30f;
                if (c0 > wr + g + 8) sacc[nt][2] = -1e30f;
                if (c1 > wr + g + 8) sacc[nt][3] = -1e30f;
            }
        }

        float tm0 = -1e30f, tm1 = -1e30f;
#pragma unroll
        for (int nt = 0; nt < 8; nt++) {
            tm0 = fmaxf(tm0, fmaxf(sacc[nt][0], sacc[nt][1]));
            tm1 = fmaxf(tm1, fmaxf(sacc[nt][2], sacc[nt][3]));
        }
        tm0 = fmaxf(tm0, __shfl_xor_sync(0xffffffffu, tm0, 1));
        tm0 = fmaxf(tm0, __shfl_xor_sync(0xffffffffu, tm0, 2));
        tm1 = fmaxf(tm1, __shfl_xor_sync(0xffffffffu, tm1, 1));
        tm1 = fmaxf(tm1, __shfl_xor_sync(0xffffffffu, tm1, 2));

        float mn0 = fmaxf(m0, tm0), mn1 = fmaxf(m1, tm1);
        float al0 = exp2f(m0 - mn0), al1 = exp2f(m1 - mn1);
        m0 = mn0; m1 = mn1;

        float rs0 = 0.f, rs1 = 0.f;
#pragma unroll
        for (int nt = 0; nt < 8; nt++) {
            sacc[nt][0] = exp2f(sacc[nt][0] - mn0);
            sacc[nt][1] = exp2f(sacc[nt][1] - mn0);
            sacc[nt][2] = exp2f(sacc[nt][2] - mn1);
            sacc[nt][3] = exp2f(sacc[nt][3] - mn1);
            rs0 += sacc[nt][0] + sacc[nt][1];
            rs1 += sacc[nt][2] + sacc[nt][3];
        }
        rs0 += __shfl_xor_sync(0xffffffffu, rs0, 1);
        rs0 += __shfl_xor_sync(0xffffffffu, rs0, 2);
        rs1 += __shfl_xor_sync(0xffffffffu, rs1, 1);
        rs1 += __shfl_xor_sync(0xffffffffu, rs1, 2);
        l0 = l0 * al0 + rs0;
        l1 = l1 * al1 + rs1;

#pragma unroll
        for (int nt = 0; nt < 8; nt++) {
            oacc[nt][0] *= al0; oacc[nt][1] *= al0;
            oacc[nt][2] *= al1; oacc[nt][3] *= al1;
        }

#pragma unroll
        for (int nt = 0; nt < 8; nt++) {
            uint2 p0 = make_uint2(f2tf(sacc[nt][0]), f2tf(sacc[nt][1]));
            uint2 p1 = make_uint2(f2tf(sacc[nt][2]), f2tf(sacc[nt][3]));
            *(uint2*)&Ps[(wr + g) * 68 + nt * 8 + 2 * tig] = p0;
            *(uint2*)&Ps[(wr + g + 8) * 68 + nt * 8 + 2 * tig] = p1;
        }
        __syncwarp();

#pragma unroll
        for (int kk = 0; kk < 64; kk += 8) {
            uint32_t a0 = Ps[(wr + g) * 68 + kk + tig];
            uint32_t a1 = Ps[(wr + g + 8) * 68 + kk + tig];
            uint32_t a2 = Ps[(wr + g) * 68 + kk + tig + 4];
            uint32_t a3 = Ps[(wr + g + 8) * 68 + kk + tig + 4];
#pragma unroll
            for (int nt = 0; nt < 8; nt++) {
                uint32_t b0 = Vs[(kk + tig) * 72 + nt * 8 + g];
                uint32_t b1 = Vs[(kk + tig + 4) * 72 + nt * 8 + g];
                mma_tf32(oacc[nt], a0, a1, a2, a3, b0, b1);
            }
        }
    }

    // normalize + tf32-round + write [b][s][h][d] (feeds Wo GEMM raw)
    float inv0 = 1.f / l0, inv1 = 1.f / l1;
    int sg0 = qt * 64 + wr + g, sg1 = sg0 + 8;
#pragma unroll
    for (int nt = 0; nt < 8; nt++) {
        int d = nt * 8 + 2 * tig;
        float2 o0 = make_float2(f2tff(oacc[nt][0] * inv0), f2tff(oacc[nt][1] * inv0));
        float2 o1 = make_float2(f2tff(oacc[nt][2] * inv1), f2tff(oacc[nt][3] * inv1));
        *(float2*)&gO[(((size_t)b * SEQ + sg0) * NH + h) * DK + d] = o0;
        *(float2*)&gO[(((size_t)b * SEQ + sg1) * NH + h) * DK + d] = o1;
    }
}

// ---------------- launch ----------------
extern "C" void kernel_launch(void* const* d_in, const int* in_sizes, int n_in,
                              void* d_out, int out_size) {
    const float* x = (const float*)d_in[0];
    const int* tpos = (const int*)d_in[1];
    const float* Wq = (const float*)d_in[2];
    const float* Wk = (const float*)d_in[3];
    const float* Wv = (const float*)d_in[4];
    const float* Wo = (const float*)d_in[5];
    float* out = (float*)d_out;

    float *gQ, *gK, *gV, *gA, *gXr, *gWr;
    cudaGetSymbolAddress((void**)&gQ, g_Q);
    cudaGetSymbolAddress((void**)&gK, g_K);
    cudaGetSymbolAddress((void**)&gV, g_V);
    cudaGetSymbolAddress((void**)&gA, g_A);
    cudaGetSymbolAddress((void**)&gXr, g_Xr);
    cudaGetSymbolAddress((void**)&gWr, g_Wr);

    cudaFuncSetAttribute(gemm_mma<1>, cudaFuncAttributeMaxDynamicSharedMemorySize,
                         GEMM_SMEM);
    cudaFuncSetAttribute(gemm_mma<0>, cudaFuncAttributeMaxDynamicSharedMemorySize,
                         GEMM_SMEM);
    cudaFuncSetAttribute(attn_tf32, cudaFuncAttributeMaxDynamicSharedMemorySize,
                         ATT_SMEM);

    // 1) round x + all W to tf32 once
    round_tf32_kernel<<<12288, 256>>>(x, Wq, Wk, Wv, Wo);

    // 2) Q/K/V projections (one launch, grid.z selects weight/dst); tf32 out
    gemm_mma<1><<<dim3(8, 64, 3), 256, GEMM_SMEM>>>(gXr, gWr, gQ, gK, gV);

    // 3) RoPE (folds Q-scale, rounds to tf32)
    const int NPAIR = BATCH * NH * SEQ * (DK / 2);
    rope_kernel<<<dim3((NPAIR + 255) / 256, 2), 256>>>(gQ, gK, tpos);

    // 4) attention (consumes raw tf32 bits; writes tf32-rounded gA)
    attn_tf32<<<dim3(SEQ / 64, NH, BATCH), 128, ATT_SMEM>>>(gQ, gK, gV, gA);

    // 5) output projection (fp32 result)
    gemm_mma<0><<<dim3(8, 64, 1), 256, GEMM_SMEM>>>(gA, gWr + (size_t)3 * DM * DM,
                                                    out, out, out);
}